// round 15
// baseline (speedup 1.0000x reference)
#include <cuda_runtime.h>
#include <stdint.h>
#include <math.h>

#define MAXB 16
#define MAXH 32
#define TPB 256
#define NCTA 740
#define SBUF_N 2064   // floats: max row (2047) + slack, 16B-multiple

__device__ unsigned g_ctr;
__global__ void reset_ctr() { g_ctr = NCTA; }

__device__ __forceinline__ void cp_async16(unsigned saddr, const void* gptr) {
    asm volatile("cp.async.ca.shared.global [%0], [%1], 16;"
                 :: "r"(saddr), "l"(gptr));
}
#define CP_COMMIT()    asm volatile("cp.async.commit_group;" ::: "memory")
#define CP_WAIT(n)     asm volatile("cp.async.wait_group %0;" :: "n"(n) : "memory")
#define BULK_COMMIT()  asm volatile("cp.async.bulk.commit_group;" ::: "memory")
// read-only wait: SMEM sources free for reuse; writes drain in background
#define BULK_WAIT_RD() asm volatile("cp.async.bulk.wait_group.read 0;" ::: "memory")
#define BULK_WAIT0()   asm volatile("cp.async.bulk.wait_group 0;" ::: "memory")
#define FENCE_ASYNC()  asm volatile("fence.proxy.async;" ::: "memory")

__device__ __forceinline__ void bulk_store(float* gdst, unsigned ssrc, unsigned bytes) {
    asm volatile("cp.async.bulk.global.shared::cta.bulk_group [%0], [%1], %2;"
                 :: "l"(gdst), "r"(ssrc), "r"(bytes) : "memory");
}

// Persistent, work-stealing, double-buffered staging; TMA bulk-store fan-out.
// Loop-top wait is READ-ONLY: the CTA never waits for its writes to drain.
__global__ void __launch_bounds__(TPB)
fused_kernel(const float* __restrict__ mask, const int* __restrict__ seq,
             const int* __restrict__ nh, float* __restrict__ out,
             unsigned out_size, unsigned S, int B) {
    __shared__ unsigned sh_s[MAXB];
    __shared__ unsigned sh_boff[MAXB];
    __shared__ unsigned sh_rp[MAXB + 1];
    __shared__ unsigned sh_H, sh_rows, sh_next;
    __shared__ __align__(16) float cbuf[2][SBUF_N];   // canonical row, dbl-buffered
    __shared__ __align__(16) float shbuf[3][SBUF_N];  // shifts 1..3

    const unsigned t = threadIdx.x;

    if (t < (unsigned)B) sh_s[t] = (unsigned)seq[t];
    if (t == 0) {
        unsigned H = nh ? (unsigned)(*nh) : 16u;
        if (H > MAXH) H = MAXH;
        if (H < 1u) H = 1u;
        sh_H = H;
    }
    __syncthreads();
    if (t == 0) {
        unsigned acc = 0, racc = 0, H = sh_H;
        for (int i = 0; i < B; ++i) {
            unsigned s = sh_s[i];
            sh_boff[i] = acc;
            sh_rp[i] = racc;
            acc += H * s * s;
            racc += s;
        }
        sh_rp[B] = racc;
        sh_rows = racc;
    }
    __syncthreads();

    const unsigned H = sh_H;
    const unsigned totalRows = sh_rows;

    auto decode = [&](unsigned w, unsigned& i, unsigned& r, unsigned& s) {
        unsigned ii = 0;
        while (ii + 1u < (unsigned)B && w >= sh_rp[ii + 1u]) ++ii;
        i = ii; r = w - sh_rp[ii]; s = sh_s[ii];
    };
    // stage row (i,r)+slack; row base 16B-aligned; overread stays in mask (r <= S-2)
    auto stage = [&](unsigned buf, unsigned i, unsigned r, unsigned s) {
        const float4* src4 = reinterpret_cast<const float4*>(
            mask + ((size_t)i * S + r) * (size_t)S);
        unsigned sb = (unsigned)__cvta_generic_to_shared(&cbuf[buf][0]);
        const unsigned nld = (s + 7u) >> 2;
        for (unsigned k = t; k < nld; k += TPB)
            cp_async16(sb + 16u * k, src4 + k);
    };

    unsigned w = blockIdx.x;
    if (w >= totalRows) return;

    unsigned ci, cr, cs;
    decode(w, ci, cr, cs);
    stage(0, ci, cr, cs);
    CP_COMMIT();
    unsigned cur = 0;

    while (true) {
        if (t == 0) sh_next = atomicAdd(&g_ctr, 1u);
        BULK_WAIT_RD();      // TMA done READING cbuf/shbuf; writes drain async
        __syncthreads();     // publishes sh_next; orders read-wait CTA-wide

        const unsigned wn = sh_next;
        const bool havenext = (wn < totalRows);
        unsigned ni = 0, nr = 0, ns = 0;
        if (havenext) {
            decode(wn, ni, nr, ns);
            stage(cur ^ 1u, ni, nr, ns);
            CP_COMMIT();
            CP_WAIT(1);      // current canonical buffer complete
        } else {
            CP_WAIT(0);
        }
        __syncthreads();     // cbuf[cur] visible CTA-wide

        const unsigned s2 = cs * cs;
        const unsigned base = sh_boff[ci] + cr * cs;
        const float* cb = cbuf[cur];

        // which shifts occur? (base + h*s2) mod 4 has period <= 4 in h
        unsigned need = 0;
        const unsigned hprobe = (H < 4u) ? H : 4u;
        for (unsigned hh = 0; hh < hprobe; ++hh) {
            unsigned lead = (4u - ((base + hh * s2) & 3u)) & 3u;
            if (lead) need |= 1u << (lead - 1u);
        }
        // build shifted copies: shbuf[b-1][k] = cb[k+b]
        const unsigned nb4 = (cs + 3u) >> 2;
        for (unsigned b = 1; b <= 3u; ++b) {
            if (!((need >> (b - 1u)) & 1u)) continue;
            float4* d4 = reinterpret_cast<float4*>(shbuf[b - 1u]);
            for (unsigned k = t; k < nb4; k += TPB) {
                unsigned e = 4u * k + b;   // reads <= cs+6 < SBUF_N (garbage ok)
                float4 R;
                R.x = cb[e]; R.y = cb[e + 1u]; R.z = cb[e + 2u]; R.w = cb[e + 3u];
                d4[k] = R;
            }
        }
        __syncthreads();     // shifted copies visible

        if (t < 32u) {       // warp 0 issues bulk stores
            FENCE_ASYNC();   // generic-proxy STS -> async-proxy TMA reads
            for (unsigned h = t; h < H; h += 32u) {
                unsigned off = base + h * s2;
                if (off >= out_size) continue;
                unsigned len = cs;
                if (len > out_size - off) len = out_size - off;
                unsigned lead = (4u - (off & 3u)) & 3u;
                if (lead > len) lead = len;
                unsigned n4 = (len - lead) >> 2;
                if (n4) {
                    const float* sp = lead ? shbuf[lead - 1u] : cb;
                    bulk_store(out + off + lead,
                               (unsigned)__cvta_generic_to_shared(sp),
                               n4 * 16u);
                }
            }
        }
        BULK_COMMIT();       // per-thread group (empty for non-issuers)

        if (t >= 128u) {     // scalar head (<4) + tail (<4) per head
            const unsigned idx = t - 128u;
            const unsigned e = idx & 7u;
            for (unsigned h = idx >> 3; h < H; h += 16u) {
                unsigned off = base + h * s2;
                if (off >= out_size) continue;
                unsigned len = cs;
                if (len > out_size - off) len = out_size - off;
                unsigned lead = (4u - (off & 3u)) & 3u;
                if (lead > len) lead = len;
                unsigned done = lead + (((len - lead) >> 2) << 2);
                if (e < 4u) {
                    if (e < lead) out[off + e] = cb[e];
                } else {
                    unsigned e2 = e - 4u;
                    if (e2 < len - done) out[off + done + e2] = cb[done + e2];
                }
            }
        }

        if (!havenext) { BULK_WAIT0(); break; }   // full drain before exit
        cur ^= 1u;
        ci = ni; cr = nr; cs = ns;
    }
}

extern "C" void kernel_launch(void* const* d_in, const int* in_sizes, int n_in,
                              void* d_out, int out_size) {
    const float* mask = (const float*)d_in[0];
    const int* seq = (const int*)d_in[1];
    const int* nh = (n_in >= 3) ? (const int*)d_in[2] : nullptr;

    int B = in_sizes[1];
    if (B > MAXB) B = MAXB;
    long long SS = (long long)in_sizes[0] / (B > 0 ? B : 1);
    unsigned S = (unsigned)(sqrt((double)SS) + 0.5);

    if (out_size <= 0) return;
    reset_ctr<<<1, 1>>>();
    fused_kernel<<<NCTA, TPB>>>(mask, seq, nh, (float*)d_out,
                                (unsigned)out_size, S, B);
}